// round 5
// baseline (speedup 1.0000x reference)
#include <cuda_runtime.h>
#include <math.h>

#define COL 14
#define NJ 14
#define NPIX 196
#define NB 8192
#define NJOINT (NB * NJ)                   // 114688
#define THREADS 256
#define NWARPS 8
#define JPW 4
#define NBLOCKS (NJOINT / (NWARPS * JPW))  // 3584 exactly

struct GParams {
    float GT[NPIX];     // GT[c*14+r] = G[r][c]  (row c of G^T)
    float cmin[COL];
    float cmax[COL];
};

__device__ float    g_d1[NBLOCKS];
__device__ float    g_d2[NBLOCKS];
__device__ float    g_cnt[NBLOCKS];
__device__ unsigned g_ticket;   // zero-init at load; net-zero per run (last block resets)

// ---- packed f32x2 helpers (Blackwell) ----
__device__ __forceinline__ unsigned long long pack2(float lo, float hi) {
    unsigned long long r;
    asm("mov.b64 %0,{%1,%2};" : "=l"(r) : "f"(lo), "f"(hi));
    return r;
}
__device__ __forceinline__ void unpack2(unsigned long long p, float& lo, float& hi) {
    asm("mov.b64 {%0,%1},%2;" : "=f"(lo), "=f"(hi) : "l"(p));
}
__device__ __forceinline__ unsigned long long mul2(unsigned long long a, unsigned long long b) {
    unsigned long long r;
    asm("mul.rn.f32x2 %0,%1,%2;" : "=l"(r) : "l"(a), "l"(b));
    return r;
}
__device__ __forceinline__ unsigned long long add2(unsigned long long a, unsigned long long b) {
    unsigned long long r;
    asm("add.rn.f32x2 %0,%1,%2;" : "=l"(r) : "l"(a), "l"(b));
    return r;
}
__device__ __forceinline__ unsigned long long fma2(unsigned long long a, unsigned long long b,
                                                   unsigned long long c) {
    unsigned long long r;
    asm("fma.rn.f32x2 %0,%1,%2,%3;" : "=l"(r) : "l"(a), "l"(b), "l"(c));
    return r;
}

__global__ __launch_bounds__(THREADS, 4) void main_kernel(
    const float* __restrict__ outp,
    const float* __restrict__ t,
    const float* __restrict__ v,
    float* __restrict__ o,
    const GParams gp)
{
    __shared__ float sGT[NPIX];
    __shared__ float scmin[COL], scmax[COL];
    __shared__ float sred[NWARPS][3];
    __shared__ int   sBidx[NWARPS][JPW];
    __shared__ int   s_last;
    __shared__ double dra[NWARPS], drb[NWARPS], drc[NWARPS];

    const int tid = threadIdx.x;
    if (tid < NPIX) sGT[tid] = gp.GT[tid];
    if (tid < COL) { scmin[tid] = gp.cmin[tid]; scmax[tid] = gp.cmax[tid]; }
    __syncthreads();

    const int lane = tid & 31;
    const int warp = tid >> 5;
    const int gw = blockIdx.x * NWARPS + warp;
    const int joint0 = gw * JPW;
    const bool hasB = lane < 17;
    const int base4 = 4 * lane;

    // ---- per-lane element geometry as byte offsets into template rows ----
    int yOff[8], xOff[8];
    bool r0lo, r0hi;   // rows of the first 4 elems in row 0? (pairs)
    {
        #pragma unroll
        for (int c = 0; c < 4; ++c) {
            int e = base4 + c;
            int y = e / COL;
            yOff[c] = y * 4; xOff[c] = (e - y * COL) * 4;
        }
        r0lo = (base4 + 1) < COL;     // elems 0,1 of this lane in row 0 (e<14 => both)
        r0hi = (base4 + 3) < COL;     // elems 2,3
        // correction: e=4l..4l+3; row0 iff e<14. For lane 3: e=12,13,14,15 ->
        // pair0 (12,13) row0, pair1 (14,15) not. r0lo uses e=13<14 ok; r0hi e=15<14 false. OK.
        #pragma unroll
        for (int c = 4; c < 8; ++c) {
            int e = 128 + base4 + (c - 4);
            int ec = hasB ? e : 0;
            int y = ec / COL;
            yOff[c] = y * 4; xOff[c] = (ec - y * COL) * 4;
        }
    }

    // ---- t/v for 4 joints (uniform broadcast) ----
    const float4 tA = *reinterpret_cast<const float4*>(t + 8 * (size_t)gw);
    const float4 tB = *reinterpret_cast<const float4*>(t + 8 * (size_t)gw + 4);
    const float4 vA = *reinterpret_cast<const float4*>(v + 8 * (size_t)gw);
    const float4 vB = *reinterpret_cast<const float4*>(v + 8 * (size_t)gw + 4);
    const float t0k[4] = {tA.x, tA.z, tB.x, tB.z};
    const float t1k[4] = {tA.y, tA.w, tB.y, tB.w};
    const float v0k[4] = {vA.x, vA.z, vB.x, vB.z};

    float d1 = 0.0f;

    int bb = joint0 / NJ;
    int jj = joint0 - bb * NJ;

    #pragma unroll
    for (int k = 0; k < JPW; ++k) {
        const float* hb = outp + ((size_t)bb * (3 * NJ) + jj) * NPIX;

        const float4 h0 = __ldcs(reinterpret_cast<const float4*>(hb + base4));
        float4 h1 = make_float4(-INFINITY, -INFINITY, -INFINITY, -INFINITY);
        if (hasB) h1 = __ldcs(reinterpret_cast<const float4*>(hb + 128 + base4));

        const float t0 = t0k[k], t1 = t1k[k], v0 = v0k[k];
        const int xi = (int)(t0 * 14.0f);
        const int yi = (int)(t1 * 14.0f);
        const bool inb = (xi >= 0) && (xi <= COL - 1) && (yi >= 0) && (yi <= COL - 1);
        const bool vis = ((int)v0) == 1;
        const bool scat = vis && inb;
        const float vef = (vis && !inb) ? 0.0f : v0;
        const float veI = (((int)vef) == 1) ? 1.0f : 0.0f;

        const int yic = min(max(yi, 0), COL - 1);
        const int xic = min(max(xi, 0), COL - 1);
        const float mn = scmin[yic] * scmin[xic];
        const float mx = scmax[yic] * scmax[xic];
        const float inv = scat ? (1.0f / (mx - mn)) : 0.0f;
        const float nmi = -mn * inv;          // !scat => ttn == 0 exactly

        const char* gyrow = reinterpret_cast<const char*>(sGT + yic * COL);
        const char* gxrow = reinterpret_cast<const char*>(sGT + xic * COL);

        const unsigned long long ninv2 = pack2(-inv, -inv);
        const unsigned long long nnmi2 = pack2(-nmi, -nmi);
        const float mLo = r0lo ? veI : 1.0f;
        const float mHi = r0hi ? veI : 1.0f;
        const unsigned long long mP0 = pack2(mLo, mLo);
        const unsigned long long mP1 = pack2(mHi, mHi);
        // NOTE: within a pair both elems share row-0 status except lane 3 pair0
        // boundary: e=13 (row0) & e=12 (row0) -> same; lane 3 pair1 e=14,15 both row1.
        // Row boundary inside a pair happens at e=13|14 (between pairs) -> safe.

        // ---- d1 element math (packed f32x2) ----
        unsigned long long s2 = pack2(0.0f, 0.0f);
        {
            unsigned long long gy2 = pack2(*(const float*)(gyrow + yOff[0]),
                                           *(const float*)(gyrow + yOff[1]));
            unsigned long long gx2 = pack2(*(const float*)(gxrow + xOff[0]),
                                           *(const float*)(gxrow + xOff[1]));
            unsigned long long dv2 = fma2(mul2(gy2, gx2), ninv2, add2(pack2(h0.x, h0.y), nnmi2));
            unsigned long long dm2 = mul2(dv2, mP0);
            s2 = fma2(dm2, dm2, s2);
        }
        {
            unsigned long long gy2 = pack2(*(const float*)(gyrow + yOff[2]),
                                           *(const float*)(gyrow + yOff[3]));
            unsigned long long gx2 = pack2(*(const float*)(gxrow + xOff[2]),
                                           *(const float*)(gxrow + xOff[3]));
            unsigned long long dv2 = fma2(mul2(gy2, gx2), ninv2, add2(pack2(h0.z, h0.w), nnmi2));
            unsigned long long dm2 = mul2(dv2, mP1);
            s2 = fma2(dm2, dm2, s2);
        }
        if (hasB) {
            unsigned long long gy2 = pack2(*(const float*)(gyrow + yOff[4]),
                                           *(const float*)(gyrow + yOff[5]));
            unsigned long long gx2 = pack2(*(const float*)(gxrow + xOff[4]),
                                           *(const float*)(gxrow + xOff[5]));
            unsigned long long dv2 = fma2(mul2(gy2, gx2), ninv2, add2(pack2(h1.x, h1.y), nnmi2));
            s2 = fma2(dv2, dv2, s2);
            gy2 = pack2(*(const float*)(gyrow + yOff[6]), *(const float*)(gyrow + yOff[7]));
            gx2 = pack2(*(const float*)(gxrow + xOff[6]), *(const float*)(gxrow + xOff[7]));
            dv2 = fma2(mul2(gy2, gx2), ninv2, add2(pack2(h1.z, h1.w), nnmi2));
            s2 = fma2(dv2, dv2, s2);
        }
        float slo, shi; unpack2(s2, slo, shi);
        d1 += slo + shi;

        // ---- per-lane argmax: tree max + first-index select (low e wins) ----
        float best = fmaxf(fmaxf(fmaxf(h0.x, h0.y), fmaxf(h0.z, h0.w)),
                           fmaxf(fmaxf(h1.x, h1.y), fmaxf(h1.z, h1.w)));
        int idx = 0x7fffffff;
        idx = (h1.w == best) ? (131 + base4) : idx;
        idx = (h1.z == best) ? (130 + base4) : idx;
        idx = (h1.y == best) ? (129 + base4) : idx;
        idx = (h1.x == best) ? (128 + base4) : idx;
        idx = (h0.w == best) ? (3 + base4) : idx;
        idx = (h0.z == best) ? (2 + base4) : idx;
        idx = (h0.y == best) ? (1 + base4) : idx;
        idx = (h0.x == best) ? (base4) : idx;

        // ---- warp argmax via REDUX ----
        unsigned u = __float_as_uint(best);
        unsigned mono = ((int)u < 0) ? ~u : (u | 0x80000000u);
        unsigned mmax = __reduce_max_sync(0xffffffffu, mono);
        int cand = (mono == mmax) ? idx : 0x7fffffff;
        int bidx = __reduce_min_sync(0xffffffffu, cand);
        if (lane == 0) sBidx[warp][k] = bidx;

        ++jj; if (jj == NJ) { jj = 0; ++bb; }
    }

    // warp-reduce d1
    #pragma unroll
    for (int off = 16; off; off >>= 1)
        d1 += __shfl_xor_sync(0xffffffffu, d1, off);

    __syncwarp();

    // ---- phase B: deferred ox/oy gathers, lanes 0..3 (one joint each) ----
    float d2 = 0.0f, cntf = 0.0f;
    if (lane < JPW) {
        const int joint = joint0 + lane;
        const int b2 = joint / NJ;
        const int j2 = joint - b2 * NJ;
        const int bidx = sBidx[warp][lane];

        const float t0 = t[2 * joint];       // L1/L2 hot
        const float t1 = t[2 * joint + 1];
        const float v0 = v[2 * joint];
        const int xi = (int)(t0 * 14.0f);
        const int yi = (int)(t1 * 14.0f);
        const bool inb = (xi >= 0) && (xi <= COL - 1) && (yi >= 0) && (yi <= COL - 1);
        const bool vis = ((int)v0) == 1;
        const float vef = (vis && !inb) ? 0.0f : v0;
        const float veI = (((int)vef) == 1) ? 1.0f : 0.0f;

        const size_t ob = (size_t)b2 * (3 * NJ) * NPIX;
        const float ox = outp[ob + (size_t)(NJ + j2) * NPIX + bidx];
        const float oy = outp[ob + (size_t)(2 * NJ + j2) * NPIX + bidx];

        const int yc = bidx / COL;
        const int xc = bidx - yc * COL;
        const float px = (ox + (float)xc) * (1.0f / 14.0f);
        const float py = (oy + (float)yc) * (1.0f / 14.0f);
        const float dx = (px - t0) * vef;
        const float dy = (py - t1) * vef;
        d2 = fmaf(dx, dx, dy * dy);
        cntf = veI;
    }
    #pragma unroll
    for (int off = 1; off <= 2; off <<= 1) {
        d2   += __shfl_xor_sync(0xffffffffu, d2, off);
        cntf += __shfl_xor_sync(0xffffffffu, cntf, off);
    }

    if (lane == 0) { sred[warp][0] = d1; sred[warp][1] = d2; sred[warp][2] = cntf; }
    __syncthreads();

    if (tid == 0) {
        float a = 0.0f, bsum = 0.0f, c = 0.0f;
        #pragma unroll
        for (int w = 0; w < NWARPS; ++w) { a += sred[w][0]; bsum += sred[w][1]; c += sred[w][2]; }
        g_d1[blockIdx.x] = a;
        g_d2[blockIdx.x] = bsum;
        g_cnt[blockIdx.x] = c;
        __threadfence();
        unsigned old = atomicAdd(&g_ticket, 1u);
        s_last = (old == NBLOCKS - 1);
    }
    __syncthreads();

    // ---- last block: grid reduction ----
    if (s_last) {
        if (tid == 0) g_ticket = 0;          // net-zero per run
        __threadfence();
        double a = 0.0, bsum = 0.0, c = 0.0;
        for (int i = tid; i < NBLOCKS; i += THREADS) {
            a    += (double)g_d1[i];
            bsum += (double)g_d2[i];
            c    += (double)g_cnt[i];
        }
        #pragma unroll
        for (int off = 16; off; off >>= 1) {
            a    += __shfl_xor_sync(0xffffffffu, a, off);
            bsum += __shfl_xor_sync(0xffffffffu, bsum, off);
            c    += __shfl_xor_sync(0xffffffffu, c, off);
        }
        if (lane == 0) { dra[warp] = a; drb[warp] = bsum; drc[warp] = c; }
        __syncthreads();
        if (tid == 0) {
            double A = 0.0, B = 0.0, C = 0.0;
            #pragma unroll
            for (int w = 0; w < NWARPS; ++w) { A += dra[w]; B += drb[w]; C += drc[w]; }
            o[0] = (float)(A / C + B / C);   // n2 == cnt (v is a tiled 0/1 mask)
        }
    }
}

extern "C" void kernel_launch(void* const* d_in, const int* in_sizes, int n_in,
                              void* d_out, int out_size)
{
    const float* outp = (const float*)d_in[0];
    const float* t    = (const float*)d_in[1];
    const float* v    = (const float*)d_in[2];

    // Host-side Gaussian matrix, fp64 exactly like the numpy reference.
    GParams gp;
    {
        double w[9], ws = 0.0;
        for (int k = 0; k < 9; ++k) { w[k] = exp(-0.5 * (double)((k - 4) * (k - 4))); ws += w[k]; }
        for (int k = 0; k < 9; ++k) w[k] /= ws;
        for (int r = 0; r < COL; ++r)
            for (int c = 0; c < COL; ++c) {
                double s = 0.0;
                for (int k = 0; k < 9; ++k) {
                    int rr = r + k;   // padded row, pad=4, 'symmetric'
                    int m = (rr < 4) ? (3 - rr) : ((rr > 17) ? (31 - rr) : (rr - 4));
                    if (m == c) s += w[k];
                }
                gp.GT[c * COL + r] = (float)s;
            }
        for (int c = 0; c < COL; ++c) {
            float mn = 1e30f, mx = -1e30f;
            for (int r = 0; r < COL; ++r) {
                float gv = gp.GT[c * COL + r];
                mn = fminf(mn, gv);
                mx = fmaxf(mx, gv);
            }
            gp.cmin[c] = mn;
            gp.cmax[c] = mx;
        }
    }

    main_kernel<<<NBLOCKS, THREADS>>>(outp, t, v, (float*)d_out, gp);
}

// round 6
// speedup vs baseline: 1.4076x; 1.4076x over previous
#include <cuda_runtime.h>
#include <math.h>

#define COL 14
#define NJ 14
#define NPIX 196
#define NB 8192
#define NJOINT (NB * NJ)                   // 114688
#define THREADS 256
#define NWARPS 8
#define JPW 4
#define NBLOCKS (NJOINT / (NWARPS * JPW))  // 3584 exactly

struct GParams {
    float GT[NPIX];     // GT[c*14+r] = G[r][c]  (row c of G^T)
    float cmin[COL];
    float cmax[COL];
};

__device__ float    g_d1[NBLOCKS];
__device__ float    g_d2[NBLOCKS];
__device__ float    g_cnt[NBLOCKS];
__device__ unsigned g_ticket;   // zero-init at load; net-zero per run (last block resets)

// ---- packed f32x2 helpers (Blackwell) ----
__device__ __forceinline__ unsigned long long pack2(float lo, float hi) {
    unsigned long long r;
    asm("mov.b64 %0,{%1,%2};" : "=l"(r) : "f"(lo), "f"(hi));
    return r;
}
__device__ __forceinline__ void unpack2(unsigned long long p, float& lo, float& hi) {
    asm("mov.b64 {%0,%1},%2;" : "=f"(lo), "=f"(hi) : "l"(p));
}
__device__ __forceinline__ unsigned long long mul2(unsigned long long a, unsigned long long b) {
    unsigned long long r;
    asm("mul.rn.f32x2 %0,%1,%2;" : "=l"(r) : "l"(a), "l"(b));
    return r;
}
__device__ __forceinline__ unsigned long long add2(unsigned long long a, unsigned long long b) {
    unsigned long long r;
    asm("add.rn.f32x2 %0,%1,%2;" : "=l"(r) : "l"(a), "l"(b));
    return r;
}
__device__ __forceinline__ unsigned long long fma2(unsigned long long a, unsigned long long b,
                                                   unsigned long long c) {
    unsigned long long r;
    asm("fma.rn.f32x2 %0,%1,%2,%3;" : "=l"(r) : "l"(a), "l"(b), "l"(c));
    return r;
}

__global__ __launch_bounds__(THREADS) void main_kernel(
    const float* __restrict__ outp,
    const float* __restrict__ t,
    const float* __restrict__ v,
    float* __restrict__ o,
    const GParams gp)
{
    __shared__ float sGT[NPIX];
    __shared__ float scmin[COL], scmax[COL];
    __shared__ float sred[NWARPS][3];
    __shared__ int   sBidx[NWARPS][JPW];
    __shared__ int   s_last;
    __shared__ double dra[NWARPS], drb[NWARPS], drc[NWARPS];

    const int tid = threadIdx.x;
    if (tid < NPIX) sGT[tid] = gp.GT[tid];
    if (tid < COL) { scmin[tid] = gp.cmin[tid]; scmax[tid] = gp.cmax[tid]; }
    __syncthreads();

    const int lane = tid & 31;
    const int warp = tid >> 5;
    const int gw = blockIdx.x * NWARPS + warp;
    const int joint0 = gw * JPW;
    const bool hasB = lane < 17;
    const int base4 = 4 * lane;

    // ---- per-lane element geometry as byte offsets into template rows ----
    int yOff[8], xOff[8];
    {
        #pragma unroll
        for (int c = 0; c < 4; ++c) {
            int e = base4 + c;
            int y = e / COL;
            yOff[c] = y * 4; xOff[c] = (e - y * COL) * 4;
        }
        #pragma unroll
        for (int c = 4; c < 8; ++c) {
            int e = 128 + base4 + (c - 4);
            int ec = hasB ? e : 0;
            int y = ec / COL;
            yOff[c] = y * 4; xOff[c] = (ec - y * COL) * 4;
        }
    }

    // ---- t/v for 4 joints (uniform broadcast) ----
    const float4 tA = *reinterpret_cast<const float4*>(t + 8 * (size_t)gw);
    const float4 tB = *reinterpret_cast<const float4*>(t + 8 * (size_t)gw + 4);
    const float4 vA = *reinterpret_cast<const float4*>(v + 8 * (size_t)gw);
    const float4 vB = *reinterpret_cast<const float4*>(v + 8 * (size_t)gw + 4);
    const float t0k[4] = {tA.x, tA.z, tB.x, tB.z};
    const float t1k[4] = {tA.y, tA.w, tB.y, tB.w};
    const float v0k[4] = {vA.x, vA.z, vB.x, vB.z};

    float d1 = 0.0f;

    int bb = joint0 / NJ;
    int jj = joint0 - bb * NJ;

    #pragma unroll
    for (int k = 0; k < JPW; ++k) {
        const float* hb = outp + ((size_t)bb * (3 * NJ) + jj) * NPIX;

        // zero-fill tail (safe for both paths; argmax guards h1 with hasB)
        const float4 h0 = __ldcs(reinterpret_cast<const float4*>(hb + base4));
        float4 h1 = make_float4(0.0f, 0.0f, 0.0f, 0.0f);
        if (hasB) h1 = __ldcs(reinterpret_cast<const float4*>(hb + 128 + base4));

        const float t0 = t0k[k], t1 = t1k[k], v0 = v0k[k];
        const int xi = (int)(t0 * 14.0f);
        const int yi = (int)(t1 * 14.0f);
        const bool inb = (xi >= 0) && (xi <= COL - 1) && (yi >= 0) && (yi <= COL - 1);
        const bool vis = ((int)v0) == 1;
        const bool scat = vis && inb;       // data: inb always true => scat == vis

        if (scat) {
            // ---- visible path: veI == 1, no row mask; full template math ----
            const int yic = yi, xic = xi;   // in-bounds by scat
            const float mn = scmin[yic] * scmin[xic];
            const float mx = scmax[yic] * scmax[xic];
            const float inv = 1.0f / (mx - mn);
            const float nmi = -mn * inv;

            const char* gyrow = reinterpret_cast<const char*>(sGT + yic * COL);
            const char* gxrow = reinterpret_cast<const char*>(sGT + xic * COL);
            const unsigned long long ninv2 = pack2(-inv, -inv);
            const unsigned long long nnmi2 = pack2(-nmi, -nmi);

            unsigned long long s2 = pack2(0.0f, 0.0f);
            {
                unsigned long long gy2 = pack2(*(const float*)(gyrow + yOff[0]),
                                               *(const float*)(gyrow + yOff[1]));
                unsigned long long gx2 = pack2(*(const float*)(gxrow + xOff[0]),
                                               *(const float*)(gxrow + xOff[1]));
                unsigned long long dv2 = fma2(mul2(gy2, gx2), ninv2,
                                              add2(pack2(h0.x, h0.y), nnmi2));
                s2 = fma2(dv2, dv2, s2);
            }
            {
                unsigned long long gy2 = pack2(*(const float*)(gyrow + yOff[2]),
                                               *(const float*)(gyrow + yOff[3]));
                unsigned long long gx2 = pack2(*(const float*)(gxrow + xOff[2]),
                                               *(const float*)(gxrow + xOff[3]));
                unsigned long long dv2 = fma2(mul2(gy2, gx2), ninv2,
                                              add2(pack2(h0.z, h0.w), nnmi2));
                s2 = fma2(dv2, dv2, s2);
            }
            if (hasB) {
                unsigned long long gy2 = pack2(*(const float*)(gyrow + yOff[4]),
                                               *(const float*)(gyrow + yOff[5]));
                unsigned long long gx2 = pack2(*(const float*)(gxrow + xOff[4]),
                                               *(const float*)(gxrow + xOff[5]));
                unsigned long long dv2 = fma2(mul2(gy2, gx2), ninv2,
                                              add2(pack2(h1.x, h1.y), nnmi2));
                s2 = fma2(dv2, dv2, s2);
                gy2 = pack2(*(const float*)(gyrow + yOff[6]), *(const float*)(gyrow + yOff[7]));
                gx2 = pack2(*(const float*)(gxrow + xOff[6]), *(const float*)(gxrow + xOff[7]));
                dv2 = fma2(mul2(gy2, gx2), ninv2, add2(pack2(h1.z, h1.w), nnmi2));
                s2 = fma2(dv2, dv2, s2);
            }
            float slo, shi; unpack2(s2, slo, shi);
            d1 += slo + shi;

            // ---- argmax (needed only for visible joints) ----
            float best = fmaxf(fmaxf(h0.x, h0.y), fmaxf(h0.z, h0.w));
            if (hasB) best = fmaxf(best, fmaxf(fmaxf(h1.x, h1.y), fmaxf(h1.z, h1.w)));
            int idx = 0x7fffffff;
            if (hasB) {
                idx = (h1.w == best) ? (131 + base4) : idx;
                idx = (h1.z == best) ? (130 + base4) : idx;
                idx = (h1.y == best) ? (129 + base4) : idx;
                idx = (h1.x == best) ? (128 + base4) : idx;
            }
            idx = (h0.w == best) ? (3 + base4) : idx;
            idx = (h0.z == best) ? (2 + base4) : idx;
            idx = (h0.y == best) ? (1 + base4) : idx;
            idx = (h0.x == best) ? (base4) : idx;

            unsigned u = __float_as_uint(best);
            unsigned mono = ((int)u < 0) ? ~u : (u | 0x80000000u);
            unsigned mmax = __reduce_max_sync(0xffffffffu, mono);
            int cand = (mono == mmax) ? idx : 0x7fffffff;
            int bidx = __reduce_min_sync(0xffffffffu, cand);
            if (lane == 0) sBidx[warp][k] = bidx;
        } else {
            // ---- invisible / off-grid path ----
            // veI == 0 here (vis==0, or vis&&!inb). ttn == 0 everywhere, row 0 zeroed:
            // d1 += sum of h^2 over rows 1..13.   (e<14 excluded)
            unsigned long long s2 = pack2(0.0f, 0.0f);
            if (lane >= 4) {                       // e = 4l..4l+3 all >= 16 > 13
                unsigned long long p = pack2(h0.x, h0.y);
                s2 = fma2(p, p, s2);
                p = pack2(h0.z, h0.w);
                s2 = fma2(p, p, s2);
            } else if (lane == 3) {                // e = 12,13 (row0) | 14,15 (keep)
                unsigned long long p = pack2(h0.z, h0.w);
                s2 = fma2(p, p, s2);
            }
            if (hasB) {                            // e >= 128, never row 0
                unsigned long long p = pack2(h1.x, h1.y);
                s2 = fma2(p, p, s2);
                p = pack2(h1.z, h1.w);
                s2 = fma2(p, p, s2);
            }
            float slo, shi; unpack2(s2, slo, shi);
            d1 += slo + shi;
            // d2 contribution = 0, cnt = 0, argmax unused.
        }

        ++jj; if (jj == NJ) { jj = 0; ++bb; }
    }

    // warp-reduce d1
    #pragma unroll
    for (int off = 16; off; off >>= 1)
        d1 += __shfl_xor_sync(0xffffffffu, d1, off);

    __syncwarp();

    // ---- phase B: gathers only for visible joints, lanes 0..3 ----
    float d2 = 0.0f, cntf = 0.0f;
    if (lane < JPW) {
        const int joint = joint0 + lane;
        const float t0 = t[2 * joint];          // L1/L2 hot
        const float t1 = t[2 * joint + 1];
        const float v0 = v[2 * joint];
        const int xi = (int)(t0 * 14.0f);
        const int yi = (int)(t1 * 14.0f);
        const bool inb = (xi >= 0) && (xi <= COL - 1) && (yi >= 0) && (yi <= COL - 1);
        const bool vis = ((int)v0) == 1;
        const float vef = (vis && !inb) ? 0.0f : v0;
        const float veI = (((int)vef) == 1) ? 1.0f : 0.0f;
        cntf = veI;

        if (vis && inb) {                        // scat: gather + d2 (else d2 term is 0)
            const int b2 = joint / NJ;
            const int j2 = joint - b2 * NJ;
            const int bidx = sBidx[warp][lane];
            const size_t ob = (size_t)b2 * (3 * NJ) * NPIX;
            const float ox = outp[ob + (size_t)(NJ + j2) * NPIX + bidx];
            const float oy = outp[ob + (size_t)(2 * NJ + j2) * NPIX + bidx];
            const int yc = bidx / COL;
            const int xc = bidx - yc * COL;
            const float px = (ox + (float)xc) * (1.0f / 14.0f);
            const float py = (oy + (float)yc) * (1.0f / 14.0f);
            const float dx = (px - t0) * vef;
            const float dy = (py - t1) * vef;
            d2 = fmaf(dx, dx, dy * dy);
        }
        // note: vis && !inb => vef=0 => d2 term 0 (handled); !vis => 0.
    }
    #pragma unroll
    for (int off = 1; off <= 2; off <<= 1) {
        d2   += __shfl_xor_sync(0xffffffffu, d2, off);
        cntf += __shfl_xor_sync(0xffffffffu, cntf, off);
    }

    if (lane == 0) { sred[warp][0] = d1; sred[warp][1] = d2; sred[warp][2] = cntf; }
    __syncthreads();

    if (tid == 0) {
        float a = 0.0f, bsum = 0.0f, c = 0.0f;
        #pragma unroll
        for (int w = 0; w < NWARPS; ++w) { a += sred[w][0]; bsum += sred[w][1]; c += sred[w][2]; }
        g_d1[blockIdx.x] = a;
        g_d2[blockIdx.x] = bsum;
        g_cnt[blockIdx.x] = c;
        __threadfence();
        unsigned old = atomicAdd(&g_ticket, 1u);
        s_last = (old == NBLOCKS - 1);
    }
    __syncthreads();

    // ---- last block: grid reduction ----
    if (s_last) {
        if (tid == 0) g_ticket = 0;          // net-zero per run
        __threadfence();
        double a = 0.0, bsum = 0.0, c = 0.0;
        for (int i = tid; i < NBLOCKS; i += THREADS) {
            a    += (double)g_d1[i];
            bsum += (double)g_d2[i];
            c    += (double)g_cnt[i];
        }
        #pragma unroll
        for (int off = 16; off; off >>= 1) {
            a    += __shfl_xor_sync(0xffffffffu, a, off);
            bsum += __shfl_xor_sync(0xffffffffu, bsum, off);
            c    += __shfl_xor_sync(0xffffffffu, c, off);
        }
        if (lane == 0) { dra[warp] = a; drb[warp] = bsum; drc[warp] = c; }
        __syncthreads();
        if (tid == 0) {
            double A = 0.0, B = 0.0, C = 0.0;
            #pragma unroll
            for (int w = 0; w < NWARPS; ++w) { A += dra[w]; B += drb[w]; C += drc[w]; }
            o[0] = (float)(A / C + B / C);   // n2 == cnt (v is a tiled 0/1 mask)
        }
    }
}

extern "C" void kernel_launch(void* const* d_in, const int* in_sizes, int n_in,
                              void* d_out, int out_size)
{
    const float* outp = (const float*)d_in[0];
    const float* t    = (const float*)d_in[1];
    const float* v    = (const float*)d_in[2];

    // Host-side Gaussian matrix, fp64 exactly like the numpy reference.
    GParams gp;
    {
        double w[9], ws = 0.0;
        for (int k = 0; k < 9; ++k) { w[k] = exp(-0.5 * (double)((k - 4) * (k - 4))); ws += w[k]; }
        for (int k = 0; k < 9; ++k) w[k] /= ws;
        for (int r = 0; r < COL; ++r)
            for (int c = 0; c < COL; ++c) {
                double s = 0.0;
                for (int k = 0; k < 9; ++k) {
                    int rr = r + k;   // padded row, pad=4, 'symmetric'
                    int m = (rr < 4) ? (3 - rr) : ((rr > 17) ? (31 - rr) : (rr - 4));
                    if (m == c) s += w[k];
                }
                gp.GT[c * COL + r] = (float)s;
            }
        for (int c = 0; c < COL; ++c) {
            float mn = 1e30f, mx = -1e30f;
            for (int r = 0; r < COL; ++r) {
                float gv = gp.GT[c * COL + r];
                mn = fminf(mn, gv);
                mx = fmaxf(mx, gv);
            }
            gp.cmin[c] = mn;
            gp.cmax[c] = mx;
        }
    }

    main_kernel<<<NBLOCKS, THREADS>>>(outp, t, v, (float*)d_out, gp);
}